// round 12
// baseline (speedup 1.0000x reference)
#include <cuda_runtime.h>
#include <math.h>

#define NPTS 1024
#define TLEN 64
#define CDIM 256
#define NTILE 16                         // 1024 / 64
#define NBLK (NTILE * (NTILE + 1) / 2)   // 136 triangular tiles

typedef unsigned int uint32;

// Scratch (__device__ globals — no allocation allowed).
__device__ uint32 g_xtf[2][NPTS * CDIM]; // tf32 means (bits)
__device__ float  g_normp[2][4][NPTS];   // per-quarter norm partials
__device__ float  g_rs[2][NPTS];         // row sums of d (atomic; init-kernel zeroed)
__device__ double g_acc[3];              // sum(dx*dy), sum(dx*dx), sum(dy*dy)
__device__ unsigned int g_qcnt[4];       // quarter completion counters
__device__ unsigned int g_ticket;        // monotonic ticket (modular check)

#define BAR1() asm volatile("bar.sync 1, 256;" ::: "memory")

__device__ __forceinline__ uint32 f2tf(float v) {
    uint32 r;
    asm("cvt.rna.tf32.f32 %0, %1;" : "=r"(r) : "f"(v));
    return r;
}
__device__ __forceinline__ void mma_tf32(float* c,
                                         uint32 a0, uint32 a1, uint32 a2, uint32 a3,
                                         uint32 b0, uint32 b1) {
    asm("mma.sync.aligned.m16n8k8.row.col.f32.tf32.tf32.f32 "
        "{%0,%1,%2,%3},{%4,%5,%6,%7},{%8,%9},{%0,%1,%2,%3};"
        : "+f"(c[0]), "+f"(c[1]), "+f"(c[2]), "+f"(c[3])
        : "r"(a0), "r"(a1), "r"(a2), "r"(a3), "r"(b0), "r"(b1));
}
__device__ __forceinline__ void wait_quarter(int q) {
    if ((threadIdx.x & 31) == 0) {
        volatile unsigned int* p = &g_qcnt[q];
        while (*p < 1024u) __nanosleep(128);
    }
    __syncwarp();
    __threadfence();
}

__global__ void init_kernel() {
    const int t = threadIdx.x;   // 256 threads
#pragma unroll
    for (int r = 0; r < 4; ++r) {
        g_rs[0][t + 256 * r] = 0.f;
        g_rs[1][t + 256 * r] = 0.f;
    }
    if (t < 4) g_qcnt[t] = 0u;
    if (t == 0) { g_acc[0] = 0.0; g_acc[1] = 0.0; g_acc[2] = 0.0; }
}

// ---------------------------------------------------------------------------
// Fused kernel: 136 blocks x 512 threads, all co-resident.
//   warps 8-15: PRODUCERS — quarter-ordered float4 time-mean (HBM-saturating)
//   warps 0-7:  CONSUMERS — r11 tf32-mma triangular gemm, chunk c gated on
//               quarter c/2; fused stats; modular-ticket finalize.
// ---------------------------------------------------------------------------
__global__ void __launch_bounds__(512, 1) fused_kernel(
    const float* __restrict__ ina, const float* __restrict__ inb,
    float* __restrict__ out) {
    const int tid  = threadIdx.x;
    const int tb   = blockIdx.x;
    const int warp = tid >> 5, lane = tid & 31;

    // ======================= PRODUCER HALF =======================
    if (warp >= 8) {
        const int pwid = tb * 8 + (warp - 8);      // 0..1087
        const int rsel = lane >> 4;                // which of 2 rows
        const int lc   = lane & 15;                // float4 slot in 64ch quarter
        if (pwid < 1024) {
            const int w     = pwid >> 9;           // matrix
            const int rpair = pwid & 511;
            const int row   = rpair * 2 + rsel;
            const float* __restrict__ src = ((w == 0) ? ina : inb)
                + (size_t)row * (TLEN * CDIM) + lc * 4;
            for (int q = 0; q < 4; ++q) {
                const float* p = src + q * 64;
                float4 a0 = make_float4(0.f, 0.f, 0.f, 0.f);
                float4 a1 = make_float4(0.f, 0.f, 0.f, 0.f);
                float4 a2 = make_float4(0.f, 0.f, 0.f, 0.f);
                float4 a3 = make_float4(0.f, 0.f, 0.f, 0.f);
#pragma unroll
                for (int t = 0; t < 16; ++t) {
                    float4 v0 = __ldcs((const float4*)(p + (size_t)(4 * t + 0) * CDIM));
                    float4 v1 = __ldcs((const float4*)(p + (size_t)(4 * t + 1) * CDIM));
                    float4 v2 = __ldcs((const float4*)(p + (size_t)(4 * t + 2) * CDIM));
                    float4 v3 = __ldcs((const float4*)(p + (size_t)(4 * t + 3) * CDIM));
                    a0.x += v0.x; a0.y += v0.y; a0.z += v0.z; a0.w += v0.w;
                    a1.x += v1.x; a1.y += v1.y; a1.z += v1.z; a1.w += v1.w;
                    a2.x += v2.x; a2.y += v2.y; a2.z += v2.z; a2.w += v2.w;
                    a3.x += v3.x; a3.y += v3.y; a3.z += v3.z; a3.w += v3.w;
                }
                const float inv = 1.0f / TLEN;
                float4 m;
                m.x = (a0.x + a1.x + a2.x + a3.x) * inv;
                m.y = (a0.y + a1.y + a2.y + a3.y) * inv;
                m.z = (a0.z + a1.z + a2.z + a3.z) * inv;
                m.w = (a0.w + a1.w + a2.w + a3.w) * inv;

                uint4 u;
                u.x = f2tf(m.x); u.y = f2tf(m.y); u.z = f2tf(m.z); u.w = f2tf(m.w);
                *(uint4*)(g_xtf[w] + (size_t)row * CDIM + q * 64 + lc * 4) = u;

                float sq = m.x * m.x + m.y * m.y + m.z * m.z + m.w * m.w;
#pragma unroll
                for (int off = 8; off > 0; off >>= 1)
                    sq += __shfl_down_sync(0xffffffffu, sq, off, 16);
                if (lc == 0) g_normp[w][q][row] = sq;

                __threadfence();
                if (lane == 0) atomicAdd(&g_qcnt[q], 1u);
            }
        }
        return;
    }

    // ======================= CONSUMER HALF (r11 gemm) =======================
    int by = (int)((__fsqrt_rn(8.f * (float)tb + 1.f) - 1.f) * 0.5f);
    while ((by + 1) * (by + 2) / 2 <= tb) ++by;
    while (by * (by + 1) / 2 > tb) --by;
    const int bx = tb - by * (by + 1) / 2;
    const bool diag = (bx == by);
    const int I = bx * 64;   // rows
    const int J = by * 64;   // cols

    __shared__ uint32 sA[2][64][36];   // [mat][m][k] tf32 bits (I-rows)
    __shared__ uint32 sB[2][64][36];   // [mat][n][k] tf32 bits (J-rows)
    __shared__ float sh_rs[2][64], sh_cs[2][64];
    __shared__ float snorm[2][128];
    __shared__ float sh_p[3][4];
    __shared__ unsigned int s_last;

    float* gyv = (float*)&sA[0][0][0]; // overlay after mainloop: 4096 floats

    const int mat = warp >> 2;             // 0: x, 1: y
    const int w4  = warp & 3;
    const int wr = w4 >> 1, wc = w4 & 1;   // 2x2 grid of 32x32 warp tiles
    const int g = lane >> 2, tig = lane & 3;

    if (tid < 128) {
        const int w2 = tid >> 6;
        sh_rs[w2][tid & 63] = 0.f;
        sh_cs[w2][tid & 63] = 0.f;
    }

    float cc[2][4][4];                     // [mi][t][q]
#pragma unroll
    for (int mi = 0; mi < 2; ++mi)
#pragma unroll
        for (int t = 0; t < 4; ++t)
#pragma unroll
            for (int q = 0; q < 4; ++q) cc[mi][t][q] = 0.f;

    // fill mapping: m = tid>>2 (0..63), kq = (tid&3)*8 : 8 uint32 (2 uint4)
    const int m  = tid >> 2;
    const int kq = (tid & 3) * 8;

    uint4 fA[2][2], fB[2][2];
    wait_quarter(0);
#pragma unroll
    for (int w = 0; w < 2; ++w)
#pragma unroll
        for (int q = 0; q < 2; ++q) {
            fA[w][q] = *(const uint4*)(g_xtf[w] + (size_t)(I + m) * CDIM + kq + 4 * q);
            fB[w][q] = *(const uint4*)(g_xtf[w] + (size_t)(J + m) * CDIM + kq + 4 * q);
        }

    const int rb0 = 32 * wr + g;           // mi=0 row base
    const int nb  = 32 * wc + g;           // col base (plus 8*t)

    for (int c = 0; c < 8; ++c) {
        BAR1();
#pragma unroll
        for (int w = 0; w < 2; ++w)
#pragma unroll
            for (int q = 0; q < 2; ++q) {
                *(uint4*)&sA[w][m][kq + 4 * q] = fA[w][q];
                *(uint4*)&sB[w][m][kq + 4 * q] = fB[w][q];
            }
        BAR1();
        if (c < 7) {
            wait_quarter((c + 1) >> 1);
            const int k0 = (c + 1) * 32;
#pragma unroll
            for (int w = 0; w < 2; ++w)
#pragma unroll
                for (int q = 0; q < 2; ++q) {
                    fA[w][q] = *(const uint4*)(g_xtf[w] + (size_t)(I + m) * CDIM + k0 + kq + 4 * q);
                    fB[w][q] = *(const uint4*)(g_xtf[w] + (size_t)(J + m) * CDIM + k0 + kq + 4 * q);
                }
        }
#pragma unroll
        for (int kk = 0; kk < 4; ++kk) {
            const int kb = kk * 8;
            uint32 av[2][4];
#pragma unroll
            for (int mi = 0; mi < 2; ++mi) {
                const int r0 = rb0 + 16 * mi, r1 = r0 + 8;
                av[mi][0] = sA[mat][r0][kb + tig];
                av[mi][1] = sA[mat][r1][kb + tig];
                av[mi][2] = sA[mat][r0][kb + tig + 4];
                av[mi][3] = sA[mat][r1][kb + tig + 4];
            }
#pragma unroll
            for (int t = 0; t < 4; ++t) {
                const int nr = nb + 8 * t;
                const uint32 b0 = sB[mat][nr][kb + tig];
                const uint32 b1 = sB[mat][nr][kb + tig + 4];
                mma_tf32(cc[0][t], av[0][0], av[0][1], av[0][2], av[0][3], b0, b1);
                mma_tf32(cc[1][t], av[1][0], av[1][1], av[1][2], av[1][3], b0, b1);
            }
        }
    }

    // norms from quarter partials (all quarters done after chunk-7 gate)
    BAR1();
    {
        const int w2 = tid & 1, r = tid >> 1;       // r = 0..127
        const int n = (r < 64) ? (I + r) : (J + r - 64);
        snorm[w2][r] = g_normp[w2][0][n] + g_normp[w2][1][n] +
                       g_normp[w2][2][n] + g_normp[w2][3][n];
    }
    BAR1();   // snorm ready; sA still holds chunk-7 data but reads done

    // -------- distances for own matrix (diag override) --------
    float dv[2][4][4];
    float pss = 0.f;                        // pxx (x-warps) / pyy (y-warps)
#pragma unroll
    for (int mi = 0; mi < 2; ++mi) {
        const int lr0 = rb0 + 16 * mi;
        const int gr0 = I + lr0, gr1 = gr0 + 8;
        const float nI0 = snorm[mat][lr0], nI1 = snorm[mat][lr0 + 8];
#pragma unroll
        for (int t = 0; t < 4; ++t) {
            const int colL = 32 * wc + 8 * t + 2 * tig;
            const int gcA = J + colL, gcB = gcA + 1;
            const float nJA = snorm[mat][64 + colL], nJB = snorm[mat][64 + colL + 1];
            float d00 = sqrtf(fmaxf(nI0 + nJA - 2.f * cc[mi][t][0], 0.f) + 1e-12f);
            float d01 = sqrtf(fmaxf(nI0 + nJB - 2.f * cc[mi][t][1], 0.f) + 1e-12f);
            float d10 = sqrtf(fmaxf(nI1 + nJA - 2.f * cc[mi][t][2], 0.f) + 1e-12f);
            float d11 = sqrtf(fmaxf(nI1 + nJB - 2.f * cc[mi][t][3], 0.f) + 1e-12f);
            if (gr0 == gcA) d00 = 1e-6f;
            if (gr0 == gcB) d01 = 1e-6f;
            if (gr1 == gcA) d10 = 1e-6f;
            if (gr1 == gcB) d11 = 1e-6f;
            dv[mi][t][0] = d00; dv[mi][t][1] = d01;
            dv[mi][t][2] = d10; dv[mi][t][3] = d11;
            pss += d00 * d00 + d01 * d01 + d10 * d10 + d11 * d11;
        }
    }

    // own-matrix row sums / col sums (smem atomics)
#pragma unroll
    for (int mi = 0; mi < 2; ++mi) {
        float pr0 = 0.f, pr1 = 0.f;
#pragma unroll
        for (int t = 0; t < 4; ++t) {
            pr0 += dv[mi][t][0] + dv[mi][t][1];
            pr1 += dv[mi][t][2] + dv[mi][t][3];
        }
        pr0 += __shfl_down_sync(0xffffffffu, pr0, 2, 4);
        pr0 += __shfl_down_sync(0xffffffffu, pr0, 1, 4);
        pr1 += __shfl_down_sync(0xffffffffu, pr1, 2, 4);
        pr1 += __shfl_down_sync(0xffffffffu, pr1, 1, 4);
        if (tig == 0) {
            atomicAdd(&sh_rs[mat][rb0 + 16 * mi],     pr0);
            atomicAdd(&sh_rs[mat][rb0 + 16 * mi + 8], pr1);
        }
    }
#pragma unroll
    for (int t = 0; t < 4; ++t) {
        const int colL = 32 * wc + 8 * t + 2 * tig;
        float vA = dv[0][t][0] + dv[0][t][2] + dv[1][t][0] + dv[1][t][2];
        float vB = dv[0][t][1] + dv[0][t][3] + dv[1][t][1] + dv[1][t][3];
#pragma unroll
        for (int s = 16; s >= 4; s >>= 1) {
            vA += __shfl_down_sync(0xffffffffu, vA, s);
            vB += __shfl_down_sync(0xffffffffu, vB, s);
        }
        if (g == 0) {
            atomicAdd(&sh_cs[mat][colL],     vA);
            atomicAdd(&sh_cs[mat][colL + 1], vB);
        }
    }

    // y-warps stage distances for the x-warps' cross product
    if (mat == 1) {
#pragma unroll
        for (int mi = 0; mi < 2; ++mi)
#pragma unroll
            for (int t = 0; t < 4; ++t)
                *(float4*)&gyv[((((w4 * 2 + mi) * 4 + t) * 32) + lane) * 4] =
                    make_float4(dv[mi][t][0], dv[mi][t][1], dv[mi][t][2], dv[mi][t][3]);
        float pyy = pss;
#pragma unroll
        for (int off = 16; off > 0; off >>= 1)
            pyy += __shfl_down_sync(0xffffffffu, pyy, off);
        if (lane == 0) sh_p[2][w4] = pyy;
    }
    BAR1();   // gyv + y-stats visible

    if (mat == 0) {
        float pxy = 0.f;
#pragma unroll
        for (int mi = 0; mi < 2; ++mi)
#pragma unroll
            for (int t = 0; t < 4; ++t) {
                const float4 dy = *(const float4*)&gyv[((((w4 * 2 + mi) * 4 + t) * 32) + lane) * 4];
                pxy += dv[mi][t][0] * dy.x + dv[mi][t][1] * dy.y +
                       dv[mi][t][2] * dy.z + dv[mi][t][3] * dy.w;
            }
        float pxx = pss;
#pragma unroll
        for (int off = 16; off > 0; off >>= 1) {
            pxy += __shfl_down_sync(0xffffffffu, pxy, off);
            pxx += __shfl_down_sync(0xffffffffu, pxx, off);
        }
        if (lane == 0) { sh_p[0][w4] = pxy; sh_p[1][w4] = pxx; }
    }
    BAR1();

    if (tid < 64) {
        atomicAdd(&g_rs[0][I + tid], sh_rs[0][tid]);
        atomicAdd(&g_rs[1][I + tid], sh_rs[1][tid]);
        if (!diag) {
            atomicAdd(&g_rs[0][J + tid], sh_cs[0][tid]);
            atomicAdd(&g_rs[1][J + tid], sh_cs[1][tid]);
        }
    }
    if (tid == 0) {
        const double scl = diag ? 1.0 : 2.0;
        double s0 = 0, s1 = 0, s2 = 0;
#pragma unroll
        for (int q = 0; q < 4; ++q) { s0 += sh_p[0][q]; s1 += sh_p[1][q]; s2 += sh_p[2][q]; }
        atomicAdd(&g_acc[0], scl * s0);
        atomicAdd(&g_acc[1], scl * s1);
        atomicAdd(&g_acc[2], scl * s2);
    }

    // -------- last-block finalize (modular ticket) --------
    __threadfence();
    BAR1();
    if (tid == 0) s_last = ((atomicAdd(&g_ticket, 1u) % NBLK) == NBLK - 1) ? 1u : 0u;
    BAR1();
    if (s_last == 0u) return;
    __threadfence();

    double sRR = 0.0, sXX = 0.0, sYY = 0.0, sX = 0.0, sY = 0.0;
#pragma unroll
    for (int q = 0; q < 4; ++q) {
        const int i = tid + q * 256;
        const double rx = (double)g_rs[0][i];
        const double ry = (double)g_rs[1][i];
        sRR += rx * ry; sXX += rx * rx; sYY += ry * ry; sX += rx; sY += ry;
    }
#pragma unroll
    for (int off = 16; off > 0; off >>= 1) {
        sRR += __shfl_down_sync(0xffffffffu, sRR, off);
        sXX += __shfl_down_sync(0xffffffffu, sXX, off);
        sYY += __shfl_down_sync(0xffffffffu, sYY, off);
        sX  += __shfl_down_sync(0xffffffffu, sX, off);
        sY  += __shfl_down_sync(0xffffffffu, sY, off);
    }
    __shared__ double sd[5][8];
    if (lane == 0) { sd[0][warp] = sRR; sd[1][warp] = sXX; sd[2][warp] = sYY; sd[3][warp] = sX; sd[4][warp] = sY; }
    BAR1();
    if (tid == 0) {
        double a0 = 0, a1 = 0, a2 = 0, a3 = 0, a4 = 0;
#pragma unroll
        for (int q = 0; q < 8; ++q) {
            a0 += sd[0][q]; a1 += sd[1][q]; a2 += sd[2][q]; a3 += sd[3][q]; a4 += sd[4][q];
        }
        const double N = (double)NPTS, N2 = N * N;
        const double sumab = g_acc[0] - (2.0 / N) * a0 + (a3 * a4) / N2;
        const double sumaa = g_acc[1] - (2.0 / N) * a1 + (a3 * a3) / N2;
        const double sumbb = g_acc[2] - (2.0 / N) * a2 + (a4 * a4) / N2;
        const double mxy = sumab / N2, mxx = sumaa / N2, myy = sumbb / N2;
        const double r = mxy / sqrt(mxx * myy + 1e-9);
        out[0] = (float)(1.0 - r);
    }
}

extern "C" void kernel_launch(void* const* d_in, const int* in_sizes, int n_in,
                              void* d_out, int out_size) {
    const float* a = (const float*)d_in[0];  // output_1 (1024,64,256) f32
    const float* b = (const float*)d_in[1];  // feature  (1024,64,256) f32
    // d_in[2] = mask, unused by the reference module.

    init_kernel<<<1, 256>>>();
    fused_kernel<<<NBLK, 512>>>(a, b, (float*)d_out);
}